// round 15
// baseline (speedup 1.0000x reference)
#include <cuda_runtime.h>
#include <cstdint>

// Problem constants
#define BQ 16
#define KCH 64
#define HF 16
#define WF 16
#define HH 40
#define WW 80
#define LY 25
#define LX 65

// Tiling: 5 x-tiles of 16 outputs, 4 ks, 16 rows; 16 chunks of 4 channels,
// double-buffered via TMA bulk copies + 2 mbarriers.
#define KC 4
#define NCHUNK 16
#define RS 112            // comp row stride words: 80 data + pad (≡16 mod 32)
#define CCS (HF*RS + 4)   // 1796: mult of 4 (align), ≡4 mod 32
#define PRS 16            // piece row stride (natural -> 1KB contiguous channel)
#define PCS (HF*PRS + 4)  // 260: ≡4 mod 32
#define CBUF (KC*CCS)     // 7184 floats
#define PBUF (KC*PCS)     // 1040 floats
#define NTHREADS 320
#define GRID (BQ*LY + BQ)

#define SMEM_FLOATS (2*CBUF + 2*PBUF)        // 16448 floats
#define SMEM_TOTAL_B (SMEM_FLOATS*4 + 32)    // + two mbarrier slots

#define N_ISSUERS 68     // 64 comp rows + 4 piece channels per chunk

extern __shared__ float smem_raw[];

// ---- packed f32x2 helpers ----
__device__ __forceinline__ unsigned long long pk2(float lo, float hi) {
    unsigned long long r;
    asm("mov.b64 %0, {%1,%2};" : "=l"(r) : "f"(lo), "f"(hi));
    return r;
}
__device__ __forceinline__ void ffma2(unsigned long long& d,
                                      unsigned long long a,
                                      unsigned long long b) {
    asm("fma.rn.f32x2 %0, %1, %2, %0;" : "+l"(d) : "l"(a), "l"(b));
}
__device__ __forceinline__ float2 unpk2(unsigned long long v) {
    float2 f;
    asm("mov.b64 {%0,%1}, %2;" : "=f"(f.x), "=f"(f.y) : "l"(v));
    return f;
}

__device__ __forceinline__ unsigned smem_addr(const void* p) {
    return (unsigned)__cvta_generic_to_shared(p);
}
__device__ __forceinline__ void bulk_g2s(unsigned dst, const void* src,
                                         unsigned bytes, unsigned mbar) {
    asm volatile(
        "cp.async.bulk.shared::cluster.global.mbarrier::complete_tx::bytes "
        "[%0], [%1], %2, [%3];"
        :: "r"(dst), "l"(src), "r"(bytes), "r"(mbar) : "memory");
}
__device__ __forceinline__ void mbar_arrive_tx(unsigned mbar, unsigned bytes) {
    asm volatile("mbarrier.arrive.expect_tx.shared::cta.b64 _, [%0], %1;"
                 :: "r"(mbar), "r"(bytes) : "memory");
}
__device__ __forceinline__ void mbar_wait(unsigned mbar, unsigned parity) {
    unsigned done;
    asm volatile(
        "{\n\t.reg .pred p;\n\t"
        "mbarrier.try_wait.parity.acquire.cta.shared::cta.b64 p, [%1], %2;\n\t"
        "selp.b32 %0, 1, 0, p;\n\t}"
        : "=r"(done) : "r"(mbar), "r"(parity) : "memory");
    if (!done) {
        asm volatile(
            "{\n\t.reg .pred P1;\n\t"
            "WL_%=:\n\t"
            "mbarrier.try_wait.parity.acquire.cta.shared::cta.b64 P1, [%0], %1, 0x989680;\n\t"
            "@P1 bra.uni WD_%=;\n\t"
            "bra.uni WL_%=;\n\t"
            "WD_%=:\n\t}"
            :: "r"(mbar), "r"(parity) : "memory");
    }
}

__global__ __launch_bounds__(NTHREADS, 3) void corr_kernel(
    const float* __restrict__ piece,
    const float* __restrict__ comp,
    const float* __restrict__ strip,
    float* __restrict__ out)
{
    float* comp_s  = smem_raw;              // 2 buffers of CBUF
    float* piece_s = smem_raw + 2*CBUF;     // 2 buffers of PBUF
    const unsigned comp_u32  = smem_addr(comp_s);
    const unsigned piece_u32 = smem_addr(piece_s);
    const unsigned mbar0 = smem_addr(smem_raw + SMEM_FLOATS);
    const unsigned mbar1 = mbar0 + 8;

    const int cta = blockIdx.x;
    const int tid = threadIdx.x;

    int b, y, srcH, kshift;
    const float* src;
    float* optr;
    if (cta < BQ*LY) {
        b = cta / LY; y = cta % LY;
        src = comp + (size_t)b * KCH * HH * WW;
        srcH = HH; kshift = 0;
        optr = out + (size_t)cta * LX;
    } else {
        b = cta - BQ*LY; y = 0;
        src = strip + (size_t)b * KCH * HF * WW;
        srcH = HF; kshift = KCH/2;   // piece_comp[k] = piece[(k+32)%64]
        optr = out + (size_t)BQ*LY*LX + (size_t)b * LX;
    }
    const float* pc = piece + (size_t)b * KCH * HF * WF;

    // issuer roles: 64 comp rows + 4 piece channels
    const bool comp_iss  = (tid < 64);
    const bool piece_iss = (tid >= 64 && tid < N_ISSUERS);
    const int  ic   = tid >> 4;            // comp channel-in-chunk 0..3
    const int  irr  = tid & 15;            // comp row 0..15
    const int  pcch = tid - 64;            // piece channel-in-chunk 0..3
    const float*  comp_src0 = src + ((size_t)ic * srcH + (y + irr)) * WW;
    const unsigned comp_dst  = comp_u32  + (unsigned)(ic*CCS + irr*RS) * 4u;
    const unsigned piece_dst = piece_u32 + (unsigned)(pcch*PCS) * 4u;

    // compute layout: phase (8 lanes) = 2 rows x 4 ks; ks stride CCS ≡ 4,
    // row stride RS ≡ 16 mod 32 words -> conflict-free aligned LDS.128.
    const int tile = tid >> 6;           // 0..4
    const int rem  = tid & 63;
    const int rp   = rem >> 2;           // 0..15 row
    const int ks   = rem & 3;            // 0..3 (lane-fastest)
    const int x0   = tile * 16;

    // one-time: zero pad words 80..95 of every channel-row, both buffers
    #pragma unroll
    for (int pass = 0; pass < 2; pass++) {
        int s = tid + pass * NTHREADS;
        if (s < 512) {
            int bufi = s >> 8;
            int c    = (s >> 6) & 3;
            int row  = (s >> 2) & 15;
            int quad = s & 3;
            *(float4*)(comp_s + bufi*CBUF + c*CCS + row*RS + 80 + quad*4) =
                make_float4(0.f, 0.f, 0.f, 0.f);
        }
    }
    if (tid == 0) {
        asm volatile("mbarrier.init.shared.b64 [%0], %1;"
                     :: "r"(mbar0), "r"(N_ISSUERS) : "memory");
        asm volatile("mbarrier.init.shared.b64 [%0], %1;"
                     :: "r"(mbar1), "r"(N_ISSUERS) : "memory");
    }
    __syncthreads();

    // accumulators: accE[tt]=(t=2tt,2tt+1) even j; accO[tt]=(t=2tt-1,2tt)
    // odd j (t=-1 and t=16 halves discarded)
    unsigned long long accE[8], accO[9];
    #pragma unroll
    for (int t = 0; t < 8; t++) accE[t] = 0ull;
    #pragma unroll
    for (int t = 0; t < 9; t++) accO[t] = 0ull;

    // prologue: issue chunk 0 -> buffer 0
    if (comp_iss) {
        mbar_arrive_tx(mbar0, WW*4);
        bulk_g2s(comp_dst, comp_src0, WW*4, mbar0);
    } else if (piece_iss) {
        mbar_arrive_tx(mbar0, HF*WF*4);
        int cg = (pcch + kshift) & (KCH - 1);
        bulk_g2s(piece_dst, pc + (size_t)cg * (HF*WF), HF*WF*4, mbar0);
    }

    #pragma unroll 1
    for (int ch = 0; ch < NCHUNK; ch++) {
        // all threads finished computing chunk ch-1 -> buffer (ch+1)&1 is free
        __syncthreads();

        if (ch + 1 < NCHUNK) {
            // prefetch chunk ch+1 into the other buffer (overlaps compute of ch)
            const int nxt = ch + 1;
            const int nb  = nxt & 1;
            const unsigned mb = nb ? mbar1 : mbar0;
            if (comp_iss) {
                mbar_arrive_tx(mb, WW*4);
                bulk_g2s(comp_dst + (unsigned)(nb*CBUF)*4u,
                         comp_src0 + (size_t)(nxt*KC) * srcH * WW, WW*4, mb);
            } else if (piece_iss) {
                mbar_arrive_tx(mb, HF*WF*4);
                int cg = (nxt*KC + pcch + kshift) & (KCH - 1);
                bulk_g2s(piece_dst + (unsigned)(nb*PBUF)*4u,
                         pc + (size_t)cg * (HF*WF), HF*WF*4, mb);
            }
        }

        // wait for chunk ch's data
        mbar_wait((ch & 1) ? mbar1 : mbar0, (unsigned)((ch >> 1) & 1));

        // ---- compute: channel ks, row rp, outputs x0..x0+15 ----
        {
            const int cb = ch & 1;
            const float* crow = comp_s + cb*CBUF + ks*CCS + rp*RS + x0;
            const float* prow = piece_s + cb*PBUF + ks*PCS + rp*PRS;
            unsigned long long wp[16];   // pairs (w[2k], w[2k+1])
            #pragma unroll
            for (int q = 0; q < 5; q++) {
                float4 v = *(const float4*)(crow + 4*q);
                wp[2*q]   = pk2(v.x, v.y);
                wp[2*q+1] = pk2(v.z, v.w);
            }
            #pragma unroll
            for (int jb = 0; jb < 4; jb++) {
                if (jb > 0) {            // JIT: quad jb+4 -> wp[2jb+8..9]
                    float4 v = *(const float4*)(crow + 4*(jb+4));
                    wp[2*jb+8] = pk2(v.x, v.y);
                    wp[2*jb+9] = pk2(v.z, v.w);
                }
                float4 pv = *(const float4*)(prow + 4*jb);
                float pj[4] = {pv.x, pv.y, pv.z, pv.w};
                #pragma unroll
                for (int jj = 0; jj < 4; jj++) {
                    const int j = 4*jb + jj;
                    unsigned long long pd = pk2(pj[jj], pj[jj]);
                    if ((j & 1) == 0) {
                        #pragma unroll
                        for (int tt = 0; tt < 8; tt++)
                            ffma2(accE[tt], pd, wp[j/2 + tt]);
                    } else {
                        #pragma unroll
                        for (int tt = 0; tt < 9; tt++)
                            ffma2(accO[tt], pd, wp[(j-1)/2 + tt]);
                    }
                }
            }
        }
    }

    // ---- fold packed banks into 16 scalars ----
    float accf[16];
    #pragma unroll
    for (int tt = 0; tt < 8; tt++) {
        float2 e = unpk2(accE[tt]);
        accf[2*tt]   = e.x;
        accf[2*tt+1] = e.y;
    }
    #pragma unroll
    for (int tt = 1; tt < 9; tt++) accf[2*tt-1] += unpk2(accO[tt]).x;
    #pragma unroll
    for (int tt = 0; tt < 8; tt++) accf[2*tt]   += unpk2(accO[tt]).y;

    // ---- cross-slice reduction: 64 partials (16 rp x 4 ks) per x ----
    __syncthreads();
    float* red  = smem_raw;            // [64][84]
    float* part = smem_raw + 64*84;    // [4][68]
    {
        int slot = rp * KC + ks;       // 0..63
        float* rb = red + slot*84 + x0;
        *(float4*)(rb +  0) = make_float4(accf[ 0],accf[ 1],accf[ 2],accf[ 3]);
        *(float4*)(rb +  4) = make_float4(accf[ 4],accf[ 5],accf[ 6],accf[ 7]);
        *(float4*)(rb +  8) = make_float4(accf[ 8],accf[ 9],accf[10],accf[11]);
        *(float4*)(rb + 12) = make_float4(accf[12],accf[13],accf[14],accf[15]);
    }
    __syncthreads();
    if (tid < 4*LX) {                  // stage 1: 4 groups of 16 slots
        int g = tid / LX;
        int x = tid - g*LX;
        float s = 0.f;
        #pragma unroll
        for (int k2 = 0; k2 < 16; k2++) s += red[(g*16 + k2)*84 + x];
        part[g*68 + x] = s;
    }
    __syncthreads();
    if (tid < LX) {                    // stage 2: fold 4 partials
        optr[tid] = part[tid] + part[68 + tid] + part[136 + tid] + part[204 + tid];
    }
}

extern "C" void kernel_launch(void* const* d_in, const int* in_sizes, int n_in,
                              void* d_out, int out_size)
{
    const float* piece = (const float*)d_in[0];   // [16,64,16,16]
    const float* comp  = (const float*)d_in[1];   // [16,64,40,80]
    const float* strip = (const float*)d_in[2];   // [16,64,16,80]
    float* out = (float*)d_out;                   // [16*25*65] ++ [16*65]

    cudaFuncSetAttribute(corr_kernel,
                         cudaFuncAttributeMaxDynamicSharedMemorySize,
                         SMEM_TOTAL_B);

    corr_kernel<<<GRID, NTHREADS, SMEM_TOTAL_B>>>(piece, comp, strip, out);
}

// round 16
// speedup vs baseline: 1.1967x; 1.1967x over previous
#include <cuda_runtime.h>
#include <cstdint>

// Problem constants
#define BQ 16
#define KCH 64
#define HF 16
#define WF 16
#define HH 40
#define WW 80
#define LY 25
#define LX 65

// Tiling: 5 x-tiles of 16 outputs (x0 = 0,16,32,48,52), 8 ks, 8 row-pairs.
// 8 chunks of 8 channels, ping-pong buffers staged by TMA bulk copies.
#define KC 8
#define NCHUNK 8
#define RS 84             // comp row stride words: 80 data + 4 zero pad
#define CCS (HF*RS + 4)   // 1348: mult of 4 (align), ≡4 mod 32 (conflict-free)
#define PRS 16            // piece row stride (1KB contiguous channel)
#define PCS (HF*PRS + 4)  // 260: ≡4 mod 32
#define CBUF (KC*CCS)     // 10784 floats
#define PBUF (KC*PCS)     // 2080 floats
#define NTHREADS 320
#define GRID (BQ*LY + BQ)

#define SMEM_FLOATS (2*(CBUF + PBUF))        // 25728 floats = 102912 B
#define SMEM_TOTAL_B (SMEM_FLOATS*4 + 32)    // + two mbarrier slots

#define N_ISSUERS 136    // 128 comp rows + 8 piece channels per chunk

extern __shared__ float smem_raw[];

// ---- packed f32x2 helpers ----
__device__ __forceinline__ unsigned long long pk2(float lo, float hi) {
    unsigned long long r;
    asm("mov.b64 %0, {%1,%2};" : "=l"(r) : "f"(lo), "f"(hi));
    return r;
}
__device__ __forceinline__ void ffma2(unsigned long long& d,
                                      unsigned long long a,
                                      unsigned long long b) {
    asm("fma.rn.f32x2 %0, %1, %2, %0;" : "+l"(d) : "l"(a), "l"(b));
}
__device__ __forceinline__ float2 unpk2(unsigned long long v) {
    float2 f;
    asm("mov.b64 {%0,%1}, %2;" : "=f"(f.x), "=f"(f.y) : "l"(v));
    return f;
}

__device__ __forceinline__ unsigned smem_addr(const void* p) {
    return (unsigned)__cvta_generic_to_shared(p);
}
__device__ __forceinline__ void bulk_g2s(unsigned dst, const void* src,
                                         unsigned bytes, unsigned mbar) {
    asm volatile(
        "cp.async.bulk.shared::cluster.global.mbarrier::complete_tx::bytes "
        "[%0], [%1], %2, [%3];"
        :: "r"(dst), "l"(src), "r"(bytes), "r"(mbar) : "memory");
}
__device__ __forceinline__ void mbar_arrive_tx(unsigned mbar, unsigned bytes) {
    asm volatile("mbarrier.arrive.expect_tx.shared::cta.b64 _, [%0], %1;"
                 :: "r"(mbar), "r"(bytes) : "memory");
}
__device__ __forceinline__ void mbar_wait(unsigned mbar, unsigned parity) {
    unsigned done;
    asm volatile(
        "{\n\t.reg .pred p;\n\t"
        "mbarrier.try_wait.parity.acquire.cta.shared::cta.b64 p, [%1], %2;\n\t"
        "selp.b32 %0, 1, 0, p;\n\t}"
        : "=r"(done) : "r"(mbar), "r"(parity) : "memory");
    if (!done) {
        asm volatile(
            "{\n\t.reg .pred P1;\n\t"
            "WL_%=:\n\t"
            "mbarrier.try_wait.parity.acquire.cta.shared::cta.b64 P1, [%0], %1, 0x989680;\n\t"
            "@P1 bra.uni WD_%=;\n\t"
            "bra.uni WL_%=;\n\t"
            "WD_%=:\n\t}"
            :: "r"(mbar), "r"(parity) : "memory");
    }
}

__global__ __launch_bounds__(NTHREADS, 2) void corr_kernel(
    const float* __restrict__ piece,
    const float* __restrict__ comp,
    const float* __restrict__ strip,
    float* __restrict__ out)
{
    float* comp_s  = smem_raw;              // 2 buffers of CBUF
    float* piece_s = smem_raw + 2*CBUF;     // 2 buffers of PBUF
    const unsigned comp_u32  = smem_addr(comp_s);
    const unsigned piece_u32 = smem_addr(piece_s);
    const unsigned mbar0 = smem_addr(smem_raw + SMEM_FLOATS);
    const unsigned mbar1 = mbar0 + 8;

    const int cta = blockIdx.x;
    const int tid = threadIdx.x;

    int b, y, srcH, kshift;
    const float* src;
    float* optr;
    if (cta < BQ*LY) {
        b = cta / LY; y = cta % LY;
        src = comp + (size_t)b * KCH * HH * WW;
        srcH = HH; kshift = 0;
        optr = out + (size_t)cta * LX;
    } else {
        b = cta - BQ*LY; y = 0;
        src = strip + (size_t)b * KCH * HF * WW;
        srcH = HF; kshift = KCH/2;   // piece_comp[k] = piece[(k+32)%64]
        optr = out + (size_t)BQ*LY*LX + (size_t)b * LX;
    }
    const float* pc = piece + (size_t)b * KCH * HF * WF;

    // issuer roles: 128 comp rows (8 ch x 16 rows) + 8 piece channels
    const bool comp_iss  = (tid < 128);
    const bool piece_iss = (tid >= 128 && tid < N_ISSUERS);
    const int  ic   = tid >> 4;            // comp channel-in-chunk 0..7
    const int  irr  = tid & 15;            // comp row 0..15
    const int  pcch = tid - 128;           // piece channel-in-chunk 0..7
    const size_t chunk_adv = (size_t)KC * srcH * WW;   // src advance per chunk
    const float* comp_src = src + ((size_t)ic * srcH + (y + irr)) * WW;
    const unsigned comp_dst  = comp_u32  + (unsigned)(ic*CCS + irr*RS) * 4u;
    const unsigned piece_dst = piece_u32 + (unsigned)(pcch*PCS) * 4u;

    // compute layout: phase (8 lanes) = 8 ks at stride CCS ≡ 16B mod 128B
    // -> conflict-free aligned LDS.128.
    const int tile = tid >> 6;           // 0..4
    const int rem  = tid & 63;
    const int rp   = rem >> 3;           // 0..7 row-pair
    const int ks   = rem & 7;            // 0..7 (lane-fastest)
    const int x0   = (tile < 4) ? tile*16 : 52;  // tile4 overlaps (benign dup)
    const int i0   = rp * 2;

    // one-time: zero pad words 80..83 of all rows, both buffers; init mbars
    if (tid < 256) {
        int bufi = tid >> 7;
        int c    = (tid >> 4) & 7;
        int row  = tid & 15;
        *(float4*)(comp_s + bufi*CBUF + c*CCS + row*RS + 80) =
            make_float4(0.f, 0.f, 0.f, 0.f);
    }
    if (tid == 0) {
        asm volatile("mbarrier.init.shared.b64 [%0], %1;"
                     :: "r"(mbar0), "r"(N_ISSUERS) : "memory");
        asm volatile("mbarrier.init.shared.b64 [%0], %1;"
                     :: "r"(mbar1), "r"(N_ISSUERS) : "memory");
    }
    __syncthreads();

    // accumulators: accE[tt]=(t=2tt,2tt+1) even j; accO[tt]=(t=2tt-1,2tt)
    // odd j (t=-1 and t=16 halves discarded)
    unsigned long long accE[8], accO[9];
    #pragma unroll
    for (int t = 0; t < 8; t++) accE[t] = 0ull;
    #pragma unroll
    for (int t = 0; t < 9; t++) accO[t] = 0ull;

    // prologue: issue chunk 0 -> buffer 0
    if (comp_iss) {
        mbar_arrive_tx(mbar0, WW*4);
        bulk_g2s(comp_dst, comp_src, WW*4, mbar0);
    } else if (piece_iss) {
        mbar_arrive_tx(mbar0, HF*WF*4);
        int cg = (pcch + kshift) & (KCH - 1);
        bulk_g2s(piece_dst, pc + (size_t)cg * (HF*WF), HF*WF*4, mbar0);
    }

    #pragma unroll 1
    for (int ch = 0; ch < NCHUNK; ch++) {
        if (ch + 1 < NCHUNK) {
            // prefetch chunk ch+1 into the other buffer; its last consumer
            // (compute of ch-1) finished before the sync at end of iter ch-1.
            const int nb = (ch + 1) & 1;
            const unsigned mb = nb ? mbar1 : mbar0;
            if (comp_iss) {
                mbar_arrive_tx(mb, WW*4);
                bulk_g2s(comp_dst + (unsigned)(nb*CBUF)*4u,
                         comp_src + chunk_adv, WW*4, mb);
            } else if (piece_iss) {
                mbar_arrive_tx(mb, HF*WF*4);
                int cg = ((ch+1)*KC + pcch + kshift) & (KCH - 1);
                bulk_g2s(piece_dst + (unsigned)(nb*PBUF)*4u,
                         pc + (size_t)cg * (HF*WF), HF*WF*4, mb);
            }
            comp_src += chunk_adv;
        }

        // wait for chunk ch (issued a full compute-chunk ago -> near-free)
        mbar_wait((ch & 1) ? mbar1 : mbar0, (unsigned)((ch >> 1) & 1));

        // ---- compute: channel ks, rows i0,i0+1, outputs x0..x0+15 ----
        {
            const int cb = ch & 1;
            const float* cbase = comp_s + cb*CBUF + ks*CCS + i0*RS + x0;
            const float* pbase = piece_s + cb*PBUF + ks*PCS + i0*PRS;
            #pragma unroll
            for (int r2 = 0; r2 < 2; r2++) {
                const float* crow = cbase + r2*RS;
                const float* prow = pbase + r2*PRS;
                unsigned long long wp[16];   // pairs (w[2k], w[2k+1])
                #pragma unroll
                for (int q = 0; q < 5; q++) {
                    float4 v = *(const float4*)(crow + 4*q);
                    wp[2*q]   = pk2(v.x, v.y);
                    wp[2*q+1] = pk2(v.z, v.w);
                }
                #pragma unroll
                for (int jb = 0; jb < 4; jb++) {
                    if (jb > 0) {            // JIT: quad jb+4 -> wp[2jb+8..9]
                        float4 v = *(const float4*)(crow + 4*(jb+4));
                        wp[2*jb+8] = pk2(v.x, v.y);
                        wp[2*jb+9] = pk2(v.z, v.w);
                    }
                    float4 pv = *(const float4*)(prow + 4*jb);
                    float pj[4] = {pv.x, pv.y, pv.z, pv.w};
                    #pragma unroll
                    for (int jj = 0; jj < 4; jj++) {
                        const int j = 4*jb + jj;
                        unsigned long long pd = pk2(pj[jj], pj[jj]);
                        if ((j & 1) == 0) {
                            #pragma unroll
                            for (int tt = 0; tt < 8; tt++)
                                ffma2(accE[tt], pd, wp[j/2 + tt]);
                        } else {
                            #pragma unroll
                            for (int tt = 0; tt < 9; tt++)
                                ffma2(accO[tt], pd, wp[(j-1)/2 + tt]);
                        }
                    }
                }
            }
        }
        // all threads done reading buf[ch&1] -> free for chunk ch+2's issue
        __syncthreads();
    }

    // ---- fold packed banks into 16 scalars ----
    float accf[16];
    #pragma unroll
    for (int tt = 0; tt < 8; tt++) {
        float2 e = unpk2(accE[tt]);
        accf[2*tt]   = e.x;
        accf[2*tt+1] = e.y;
    }
    #pragma unroll
    for (int tt = 1; tt < 9; tt++) accf[2*tt-1] += unpk2(accO[tt]).x;
    #pragma unroll
    for (int tt = 0; tt < 8; tt++) accf[2*tt]   += unpk2(accO[tt]).y;

    // ---- cross-slice reduction: 64 partials (8 rp x 8 ks) per x ----
    // (no extra sync needed: loop ended with __syncthreads)
    float* red  = smem_raw;            // [64][84]
    float* part = smem_raw + 64*84;    // [4][68]
    {
        int slot = rp * KC + ks;
        float* rb = red + slot*84 + x0;
        *(float4*)(rb +  0) = make_float4(accf[ 0],accf[ 1],accf[ 2],accf[ 3]);
        *(float4*)(rb +  4) = make_float4(accf[ 4],accf[ 5],accf[ 6],accf[ 7]);
        *(float4*)(rb +  8) = make_float4(accf[ 8],accf[ 9],accf[10],accf[11]);
        *(float4*)(rb + 12) = make_float4(accf[12],accf[13],accf[14],accf[15]);
    }
    __syncthreads();
    if (tid < 4*LX) {                  // stage 1: 4 groups of 16 slots
        int g = tid / LX;
        int x = tid - g*LX;
        float s = 0.f;
        #pragma unroll
        for (int k2 = 0; k2 < 16; k2++) s += red[(g*16 + k2)*84 + x];
        part[g*68 + x] = s;
    }
    __syncthreads();
    if (tid < LX) {                    // stage 2: fold 4 partials
        optr[tid] = part[tid] + part[68 + tid] + part[136 + tid] + part[204 + tid];
    }
}

extern "C" void kernel_launch(void* const* d_in, const int* in_sizes, int n_in,
                              void* d_out, int out_size)
{
    const float* piece = (const float*)d_in[0];   // [16,64,16,16]
    const float* comp  = (const float*)d_in[1];   // [16,64,40,80]
    const float* strip = (const float*)d_in[2];   // [16,64,16,80]
    float* out = (float*)d_out;                   // [16*25*65] ++ [16*65]

    cudaFuncSetAttribute(corr_kernel,
                         cudaFuncAttributeMaxDynamicSharedMemorySize,
                         SMEM_TOTAL_B);

    corr_kernel<<<GRID, NTHREADS, SMEM_TOTAL_B>>>(piece, comp, strip, out);
}

// round 17
// speedup vs baseline: 1.2638x; 1.0560x over previous
#include <cuda_runtime.h>
#include <cstdint>

// Problem constants
#define BQ 16
#define KCH 64
#define HF 16
#define WF 16
#define HH 40
#define WW 80
#define LY 25
#define LX 65

// Tiling: 4 full x-tiles of 16 (x0=0,16,32,48) + group4 computing column 64.
// 8 chunks of 8 channels, ping-pong buffers staged by TMA bulk copies.
#define KC 8
#define NCHUNK 8
#define RS 80             // comp row stride words: exactly the data (no pad)
#define CCS (HF*RS + 4)   // 1284: mult of 4 (align), ≡4 mod 32 (conflict-free)
#define PRS 16            // piece row stride (1KB contiguous channel)
#define PCS (HF*PRS + 4)  // 260: ≡4 mod 32
#define CBUF (KC*CCS)     // 10272 floats
#define PBUF (KC*PCS)     // 2080 floats
#define NTHREADS 320
#define GRID (BQ*LY + BQ)

#define SMEM_FLOATS (2*(CBUF + PBUF))        // 24704 floats = 98816 B
#define SMEM_TOTAL_B (SMEM_FLOATS*4 + 32)    // + two mbarrier slots

#define N_ISSUERS 136    // 128 comp rows + 8 piece channels per chunk

extern __shared__ float smem_raw[];

// ---- packed f32x2 helpers ----
__device__ __forceinline__ unsigned long long pk2(float lo, float hi) {
    unsigned long long r;
    asm("mov.b64 %0, {%1,%2};" : "=l"(r) : "f"(lo), "f"(hi));
    return r;
}
__device__ __forceinline__ void ffma2(unsigned long long& d,
                                      unsigned long long a,
                                      unsigned long long b) {
    asm("fma.rn.f32x2 %0, %1, %2, %0;" : "+l"(d) : "l"(a), "l"(b));
}
__device__ __forceinline__ float2 unpk2(unsigned long long v) {
    float2 f;
    asm("mov.b64 {%0,%1}, %2;" : "=f"(f.x), "=f"(f.y) : "l"(v));
    return f;
}

__device__ __forceinline__ unsigned smem_addr(const void* p) {
    return (unsigned)__cvta_generic_to_shared(p);
}
__device__ __forceinline__ void bulk_g2s(unsigned dst, const void* src,
                                         unsigned bytes, unsigned mbar) {
    asm volatile(
        "cp.async.bulk.shared::cluster.global.mbarrier::complete_tx::bytes "
        "[%0], [%1], %2, [%3];"
        :: "r"(dst), "l"(src), "r"(bytes), "r"(mbar) : "memory");
}
__device__ __forceinline__ void mbar_arrive_tx(unsigned mbar, unsigned bytes) {
    asm volatile("mbarrier.arrive.expect_tx.shared::cta.b64 _, [%0], %1;"
                 :: "r"(mbar), "r"(bytes) : "memory");
}
__device__ __forceinline__ void mbar_wait(unsigned mbar, unsigned parity) {
    unsigned done;
    asm volatile(
        "{\n\t.reg .pred p;\n\t"
        "mbarrier.try_wait.parity.acquire.cta.shared::cta.b64 p, [%1], %2;\n\t"
        "selp.b32 %0, 1, 0, p;\n\t}"
        : "=r"(done) : "r"(mbar), "r"(parity) : "memory");
    if (!done) {
        asm volatile(
            "{\n\t.reg .pred P1;\n\t"
            "WL_%=:\n\t"
            "mbarrier.try_wait.parity.acquire.cta.shared::cta.b64 P1, [%0], %1, 0x989680;\n\t"
            "@P1 bra.uni WD_%=;\n\t"
            "bra.uni WL_%=;\n\t"
            "WD_%=:\n\t}"
            :: "r"(mbar), "r"(parity) : "memory");
    }
}

__global__ __launch_bounds__(NTHREADS, 2) void corr_kernel(
    const float* __restrict__ piece,
    const float* __restrict__ comp,
    const float* __restrict__ strip,
    float* __restrict__ out)
{
    float* comp_s  = smem_raw;              // 2 buffers of CBUF
    float* piece_s = smem_raw + 2*CBUF;     // 2 buffers of PBUF
    const unsigned comp_u32  = smem_addr(comp_s);
    const unsigned piece_u32 = smem_addr(piece_s);
    const unsigned mbar0 = smem_addr(smem_raw + SMEM_FLOATS);
    const unsigned mbar1 = mbar0 + 8;

    const int cta = blockIdx.x;
    const int tid = threadIdx.x;

    int b, y, srcH, kshift;
    const float* src;
    float* optr;
    if (cta < BQ*LY) {
        b = cta / LY; y = cta % LY;
        src = comp + (size_t)b * KCH * HH * WW;
        srcH = HH; kshift = 0;
        optr = out + (size_t)cta * LX;
    } else {
        b = cta - BQ*LY; y = 0;
        src = strip + (size_t)b * KCH * HF * WW;
        srcH = HF; kshift = KCH/2;   // piece_comp[k] = piece[(k+32)%64]
        optr = out + (size_t)BQ*LY*LX + (size_t)b * LX;
    }
    const float* pc = piece + (size_t)b * KCH * HF * WF;

    // issuer roles: 128 comp rows (8 ch x 16 rows) + 8 piece channels
    const bool comp_iss  = (tid < 128);
    const bool piece_iss = (tid >= 128 && tid < N_ISSUERS);
    const int  ic   = tid >> 4;
    const int  irr  = tid & 15;
    const int  pcch = tid - 128;
    const size_t chunk_adv = (size_t)KC * srcH * WW;
    const float* comp_src = src + ((size_t)ic * srcH + (y + irr)) * WW;
    const unsigned comp_dst  = comp_u32  + (unsigned)(ic*CCS + irr*RS) * 4u;
    const unsigned piece_dst = piece_u32 + (unsigned)(pcch*PCS) * 4u;

    // compute layout: phase (8 lanes) = 8 ks at stride CCS ≡ 16B mod 128B
    const int tile = tid >> 6;           // 0..3 = 16-wide tiles; 4 = column 64
    const int rem  = tid & 63;
    const int rp   = rem >> 3;           // 0..7 row-pair
    const int ks   = rem & 7;            // 0..7 (lane-fastest)
    const int x0   = tile * 16;          // group 4 uses x=64 directly
    const int i0   = rp * 2;

    if (tid == 0) {
        asm volatile("mbarrier.init.shared.b64 [%0], %1;"
                     :: "r"(mbar0), "r"(N_ISSUERS) : "memory");
        asm volatile("mbarrier.init.shared.b64 [%0], %1;"
                     :: "r"(mbar1), "r"(N_ISSUERS) : "memory");
    }
    __syncthreads();

    // tile accumulators (groups 0-3): accE[tt]=(t=2tt,2tt+1) even j;
    // accO[tt]=(t=2tt-1,2tt) odd j. group 4: scalar acc64 for x=64.
    unsigned long long accE[8], accO[9];
    float acc64 = 0.f;
    #pragma unroll
    for (int t = 0; t < 8; t++) accE[t] = 0ull;
    #pragma unroll
    for (int t = 0; t < 9; t++) accO[t] = 0ull;

    // prologue: issue chunk 0 -> buffer 0
    if (comp_iss) {
        mbar_arrive_tx(mbar0, WW*4);
        bulk_g2s(comp_dst, comp_src, WW*4, mbar0);
    } else if (piece_iss) {
        mbar_arrive_tx(mbar0, HF*WF*4);
        int cg = (pcch + kshift) & (KCH - 1);
        bulk_g2s(piece_dst, pc + (size_t)cg * (HF*WF), HF*WF*4, mbar0);
    }

    #pragma unroll 1
    for (int ch = 0; ch < NCHUNK; ch++) {
        if (ch + 1 < NCHUNK) {
            const int nb = (ch + 1) & 1;
            const unsigned mb = nb ? mbar1 : mbar0;
            if (comp_iss) {
                mbar_arrive_tx(mb, WW*4);
                bulk_g2s(comp_dst + (unsigned)(nb*CBUF)*4u,
                         comp_src + chunk_adv, WW*4, mb);
            } else if (piece_iss) {
                mbar_arrive_tx(mb, HF*WF*4);
                int cg = ((ch+1)*KC + pcch + kshift) & (KCH - 1);
                bulk_g2s(piece_dst + (unsigned)(nb*PBUF)*4u,
                         pc + (size_t)cg * (HF*WF), HF*WF*4, mb);
            }
            comp_src += chunk_adv;
        }

        // wait for chunk ch (issued a full compute-chunk earlier)
        mbar_wait((ch & 1) ? mbar1 : mbar0, (unsigned)((ch >> 1) & 1));

        const int cb = ch & 1;
        if (tile < 4) {
            // ---- 16-wide tile: channel ks, rows i0,i0+1, x0..x0+15 ----
            const float* cbase = comp_s + cb*CBUF + ks*CCS + i0*RS + x0;
            const float* pbase = piece_s + cb*PBUF + ks*PCS + i0*PRS;
            #pragma unroll
            for (int r2 = 0; r2 < 2; r2++) {
                const float* crow = cbase + r2*RS;
                const float* prow = pbase + r2*PRS;
                unsigned long long wp[16];   // pairs (w[2k], w[2k+1])
                #pragma unroll
                for (int q = 0; q < 5; q++) {   // direct u64 pairs, no MOV
                    ulonglong2 v = *(const ulonglong2*)(crow + 4*q);
                    wp[2*q]   = v.x;
                    wp[2*q+1] = v.y;
                }
                #pragma unroll
                for (int jb = 0; jb < 4; jb++) {
                    if (jb > 0) {            // JIT: quad jb+4 -> wp[2jb+8..9]
                        ulonglong2 v = *(const ulonglong2*)(crow + 4*(jb+4));
                        wp[2*jb+8] = v.x;
                        wp[2*jb+9] = v.y;
                    }
                    float4 pv = *(const float4*)(prow + 4*jb);
                    float pj[4] = {pv.x, pv.y, pv.z, pv.w};
                    #pragma unroll
                    for (int jj = 0; jj < 4; jj++) {
                        const int j = 4*jb + jj;
                        unsigned long long pd = pk2(pj[jj], pj[jj]);
                        if ((j & 1) == 0) {
                            #pragma unroll
                            for (int tt = 0; tt < 8; tt++)
                                ffma2(accE[tt], pd, wp[j/2 + tt]);
                        } else {
                            #pragma unroll
                            for (int tt = 0; tt < 9; tt++)
                                ffma2(accO[tt], pd, wp[(j-1)/2 + tt]);
                        }
                    }
                }
            }
        } else {
            // ---- group 4: single column x=64, scalar ----
            const float* cbase = comp_s + cb*CBUF + ks*CCS + i0*RS + 64;
            const float* pbase = piece_s + cb*PBUF + ks*PCS + i0*PRS;
            #pragma unroll
            for (int r2 = 0; r2 < 2; r2++) {
                const float* crow = cbase + r2*RS;
                const float* prow = pbase + r2*PRS;
                float w[16], p[16];
                #pragma unroll
                for (int q = 0; q < 4; q++) {
                    *(float4*)(w + 4*q) = *(const float4*)(crow + 4*q);
                    *(float4*)(p + 4*q) = *(const float4*)(prow + 4*q);
                }
                #pragma unroll
                for (int j = 0; j < 16; j++) acc64 += p[j] * w[j];
            }
        }
        // all threads done reading buf[ch&1]
        __syncthreads();
    }

    // ---- cross-slice reduction: 64 partials (8 rp x 8 ks), 65 columns ----
    float* red  = smem_raw;            // [64][68]
    float* part = smem_raw + 64*68;    // [4][68]
    const int slot = rp * KC + ks;
    if (tile < 4) {
        float accf[16];
        #pragma unroll
        for (int tt = 0; tt < 8; tt++) {
            float2 e = unpk2(accE[tt]);
            accf[2*tt]   = e.x;
            accf[2*tt+1] = e.y;
        }
        #pragma unroll
        for (int tt = 1; tt < 9; tt++) accf[2*tt-1] += unpk2(accO[tt]).x;
        #pragma unroll
        for (int tt = 0; tt < 8; tt++) accf[2*tt]   += unpk2(accO[tt]).y;
        float* rb = red + slot*68 + x0;
        *(float4*)(rb +  0) = make_float4(accf[ 0],accf[ 1],accf[ 2],accf[ 3]);
        *(float4*)(rb +  4) = make_float4(accf[ 4],accf[ 5],accf[ 6],accf[ 7]);
        *(float4*)(rb +  8) = make_float4(accf[ 8],accf[ 9],accf[10],accf[11]);
        *(float4*)(rb + 12) = make_float4(accf[12],accf[13],accf[14],accf[15]);
    } else {
        red[slot*68 + 64] = acc64;
    }
    __syncthreads();
    if (tid < 4*LX) {                  // stage 1: 4 groups of 16 slots
        int g = tid / LX;
        int x = tid - g*LX;
        float s = 0.f;
        #pragma unroll
        for (int k2 = 0; k2 < 16; k2++) s += red[(g*16 + k2)*68 + x];
        part[g*68 + x] = s;
    }
    __syncthreads();
    if (tid < LX) {                    // stage 2: fold 4 partials
        optr[tid] = part[tid] + part[68 + tid] + part[136 + tid] + part[204 + tid];
    }
}

extern "C" void kernel_launch(void* const* d_in, const int* in_sizes, int n_in,
                              void* d_out, int out_size)
{
    const float* piece = (const float*)d_in[0];   // [16,64,16,16]
    const float* comp  = (const float*)d_in[1];   // [16,64,40,80]
    const float* strip = (const float*)d_in[2];   // [16,64,16,80]
    float* out = (float*)d_out;                   // [16*25*65] ++ [16*65]

    cudaFuncSetAttribute(corr_kernel,
                         cudaFuncAttributeMaxDynamicSharedMemorySize,
                         SMEM_TOTAL_B);

    corr_kernel<<<GRID, NTHREADS, SMEM_TOTAL_B>>>(piece, comp, strip, out);
}